// round 3
// baseline (speedup 1.0000x reference)
#include <cuda_runtime.h>
#include <cuda_bf16.h>

// Problem constants (fixed shapes per reference)
#define B 2048
#define C 1024
#define TEMP_INV 0.5f
#define EPS_INV 10.0f      // 1/0.1
#define N_ITERS 20
#define LOSS_SCALE 0.001f

// ---------------- scratch (device globals; no allocation allowed) ----------
__device__ float g_ps[B * C];       // softmax(y_s/2)
__device__ float g_pt[B * C];       // softmax(y_t/2)
__device__ float g_W [B * B];       // L1 cdist
__device__ float g_K [B * B];       // exp(-W/eps)
__device__ float g_a [B];           // row scaling
__device__ float g_b [B];           // col scaling
__device__ float g_lp[B];           // per-row loss partials

// ---------------- helpers ---------------------------------------------------
__device__ __forceinline__ float blockReduceSum256(float v) {
    __shared__ float sm[8];
    #pragma unroll
    for (int o = 16; o > 0; o >>= 1) v += __shfl_down_sync(0xffffffffu, v, o);
    int lane = threadIdx.x & 31, w = threadIdx.x >> 5;
    if (lane == 0) sm[w] = v;
    __syncthreads();
    if (w == 0) {
        v = (lane < 8) ? sm[lane] : 0.0f;
        #pragma unroll
        for (int o = 4; o > 0; o >>= 1) v += __shfl_down_sync(0xffu, v, o);
    }
    return v;  // valid in thread 0
}

// ---------------- softmax: one block per row (4096 rows total) --------------
__global__ __launch_bounds__(256) void softmax_kernel(const float* __restrict__ ys,
                                                      const float* __restrict__ yt) {
    int row = blockIdx.x;
    const float* src = (row < B) ? (ys + (size_t)row * C) : (yt + (size_t)(row - B) * C);
    float*       dst = (row < B) ? (g_ps + (size_t)row * C) : (g_pt + (size_t)(row - B) * C);
    int tid = threadIdx.x;

    float4 x = ((const float4*)src)[tid];
    x.x *= TEMP_INV; x.y *= TEMP_INV; x.z *= TEMP_INV; x.w *= TEMP_INV;

    __shared__ float smx[8];
    __shared__ float bc;

    // block max
    float m = fmaxf(fmaxf(x.x, x.y), fmaxf(x.z, x.w));
    #pragma unroll
    for (int o = 16; o > 0; o >>= 1) m = fmaxf(m, __shfl_down_sync(0xffffffffu, m, o));
    int lane = tid & 31, w = tid >> 5;
    if (lane == 0) smx[w] = m;
    __syncthreads();
    if (w == 0) {
        m = (lane < 8) ? smx[lane] : -1e30f;
        #pragma unroll
        for (int o = 4; o > 0; o >>= 1) m = fmaxf(m, __shfl_down_sync(0xffu, m, o));
        if (lane == 0) bc = m;
    }
    __syncthreads();
    m = bc;

    float4 e;
    e.x = __expf(x.x - m); e.y = __expf(x.y - m);
    e.z = __expf(x.z - m); e.w = __expf(x.w - m);
    float s = (e.x + e.y) + (e.z + e.w);

    // block sum
    #pragma unroll
    for (int o = 16; o > 0; o >>= 1) s += __shfl_down_sync(0xffffffffu, s, o);
    __syncthreads();
    if (lane == 0) smx[w] = s;
    __syncthreads();
    if (w == 0) {
        s = (lane < 8) ? smx[lane] : 0.0f;
        #pragma unroll
        for (int o = 4; o > 0; o >>= 1) s += __shfl_down_sync(0xffu, s, o);
        if (lane == 0) bc = s;
    }
    __syncthreads();
    float inv = __fdividef(1.0f, bc);

    e.x *= inv; e.y *= inv; e.z *= inv; e.w *= inv;
    ((float4*)dst)[tid] = e;
}

// ---------------- init b = 1 ------------------------------------------------
__global__ void initb_kernel() {
    int i = blockIdx.x * blockDim.x + threadIdx.x;
    if (i < B) g_b[i] = 1.0f;
}

// ---------------- cdist L1 + K = exp(-W/eps) --------------------------------
// 128x128 tile per block, 256 threads, 8x8 register blocking, KC=32.
#define TM 128
#define TN 128
#define KC 32
#define LDT 33  // pad: conflict-free scalar LDS/STS

__global__ __launch_bounds__(256, 2) void cdist_kernel() {
    __shared__ float As[TM * LDT];
    __shared__ float Bs[TN * LDT];

    int bi = blockIdx.y, bj = blockIdx.x;
    int tid = threadIdx.x;
    int tx = tid & 15, ty = tid >> 4;

    const float* Abase = g_ps + (size_t)(bi * TM) * C;
    const float* Bbase = g_pt + (size_t)(bj * TN) * C;

    float acc[8][8];
    #pragma unroll
    for (int r = 0; r < 8; r++)
        #pragma unroll
        for (int c = 0; c < 8; c++) acc[r][c] = 0.0f;

    for (int k0 = 0; k0 < C; k0 += KC) {
        // load tiles: 1024 float4 per tile, 4 per thread; store row-major [row][k]
        #pragma unroll
        for (int l = 0; l < 4; l++) {
            int v   = tid + l * 256;       // 0..1023
            int row = v >> 3;              // 0..127
            int kq  = (v & 7) << 2;        // 0,4,..,28
            float4 a4 = *(const float4*)(Abase + (size_t)row * C + k0 + kq);
            As[row * LDT + kq + 0] = a4.x;
            As[row * LDT + kq + 1] = a4.y;
            As[row * LDT + kq + 2] = a4.z;
            As[row * LDT + kq + 3] = a4.w;
            float4 b4 = *(const float4*)(Bbase + (size_t)row * C + k0 + kq);
            Bs[row * LDT + kq + 0] = b4.x;
            Bs[row * LDT + kq + 1] = b4.y;
            Bs[row * LDT + kq + 2] = b4.z;
            Bs[row * LDT + kq + 3] = b4.w;
        }
        __syncthreads();

        #pragma unroll 4
        for (int k = 0; k < KC; k++) {
            float af[8], bf[8];
            #pragma unroll
            for (int r = 0; r < 8; r++) af[r] = As[(ty * 8 + r) * LDT + k];
            #pragma unroll
            for (int c = 0; c < 8; c++) bf[c] = Bs[(tx * 8 + c) * LDT + k];
            #pragma unroll
            for (int r = 0; r < 8; r++)
                #pragma unroll
                for (int c = 0; c < 8; c++)
                    acc[r][c] += fabsf(af[r] - bf[c]);
        }
        __syncthreads();
    }

    // epilogue: W and K
    #pragma unroll
    for (int r = 0; r < 8; r++) {
        int row = bi * TM + ty * 8 + r;
        float* wrow = g_W + (size_t)row * B + bj * TN + tx * 8;
        float* krow = g_K + (size_t)row * B + bj * TN + tx * 8;
        #pragma unroll
        for (int c4 = 0; c4 < 2; c4++) {
            float4 wv = make_float4(acc[r][c4*4+0], acc[r][c4*4+1],
                                    acc[r][c4*4+2], acc[r][c4*4+3]);
            ((float4*)wrow)[c4] = wv;
            float4 kv = make_float4(__expf(-EPS_INV * wv.x), __expf(-EPS_INV * wv.y),
                                    __expf(-EPS_INV * wv.z), __expf(-EPS_INV * wv.w));
            ((float4*)krow)[c4] = kv;
        }
    }
}

// ---------------- Sinkhorn matvecs ------------------------------------------
// a_i = 1 / sum_j K[i][j] * b[j]   : one block per row
__global__ __launch_bounds__(256) void rowmv_kernel() {
    int row = blockIdx.x, tid = threadIdx.x;
    const float4* Kr = (const float4*)(g_K + (size_t)row * B);
    const float4* b4 = (const float4*)g_b;
    float s = 0.0f;
    #pragma unroll
    for (int l = 0; l < 2; l++) {
        int t = tid + l * 256;
        float4 k4 = Kr[t], bb = b4[t];
        s += k4.x * bb.x + k4.y * bb.y + k4.z * bb.z + k4.w * bb.w;
    }
    s = blockReduceSum256(s);
    if (tid == 0) g_a[row] = __fdividef(1.0f, s);
}

// b_j = 1 / sum_i K[i][j] * a[i]   : 128 blocks x (16 cols, 16 row-groups)
__global__ __launch_bounds__(256) void colmv_kernel() {
    int tid = threadIdx.x;
    int c  = tid & 15;
    int rg = tid >> 4;
    int col = blockIdx.x * 16 + c;
    const float* Kc = g_K + col;
    float s = 0.0f;
    int i0 = rg * 128;
    #pragma unroll 4
    for (int i = i0; i < i0 + 128; i++)
        s += Kc[(size_t)i * B] * g_a[i];

    __shared__ float sm[256];
    sm[tid] = s;
    __syncthreads();
    #pragma unroll
    for (int off = 128; off >= 16; off >>= 1) {
        if (tid < off) sm[tid] += sm[tid + off];
        __syncthreads();
    }
    if (tid < 16) g_b[blockIdx.x * 16 + tid] = __fdividef(1.0f, sm[tid]);
}

// ---------------- loss -------------------------------------------------------
__global__ __launch_bounds__(256) void loss_row_kernel() {
    int row = blockIdx.x, tid = threadIdx.x;
    const float4* Kr = (const float4*)(g_K + (size_t)row * B);
    const float4* Wr = (const float4*)(g_W + (size_t)row * B);
    const float4* b4 = (const float4*)g_b;
    float s = 0.0f;
    #pragma unroll
    for (int l = 0; l < 2; l++) {
        int t = tid + l * 256;
        float4 k4 = Kr[t], w4 = Wr[t], bb = b4[t];
        s += k4.x * w4.x * bb.x + k4.y * w4.y * bb.y
           + k4.z * w4.z * bb.z + k4.w * w4.w * bb.w;
    }
    s = blockReduceSum256(s);
    if (tid == 0) g_lp[row] = g_a[row] * s;
}

__global__ __launch_bounds__(256) void loss_final_kernel(float* __restrict__ out) {
    int tid = threadIdx.x;
    float s = 0.0f;
    #pragma unroll
    for (int l = 0; l < 8; l++) s += g_lp[tid + l * 256];
    s = blockReduceSum256(s);
    if (tid == 0) out[0] = LOSS_SCALE * s;
}

// ---------------- launcher ---------------------------------------------------
extern "C" void kernel_launch(void* const* d_in, const int* in_sizes, int n_in,
                              void* d_out, int out_size) {
    const float* ys = (const float*)d_in[0];
    const float* yt = (const float*)d_in[1];
    float* out = (float*)d_out;

    softmax_kernel<<<2 * B, 256>>>(ys, yt);
    initb_kernel<<<8, 256>>>();
    cdist_kernel<<<dim3(B / TN, B / TM), 256>>>();

    for (int it = 0; it < N_ITERS; it++) {
        rowmv_kernel<<<B, 256>>>();
        colmv_kernel<<<B / 16, 256>>>();
    }

    loss_row_kernel<<<B, 256>>>();
    loss_final_kernel<<<1, 256>>>(out);
}

// round 5
// speedup vs baseline: 1.0597x; 1.0597x over previous
#include <cuda_runtime.h>
#include <cuda_bf16.h>

#define B 2048
#define C 1024
#define TEMP_INV 0.5f
#define EPS_INV 10.0f
#define N_ITERS 20
#define LOSS_SCALE 0.001f

typedef unsigned long long u64;
typedef unsigned int u32;

// ---------------- scratch (device globals; no runtime allocation) -----------
__device__ float g_ps[B * C];
__device__ float g_pt[B * C];
__device__ float g_W [B * B];
__device__ float g_K [B * B];
__device__ float g_Kt[B * B];       // K transposed, for the column matvec
__device__ float g_a [B];
__device__ float g_b [B];
__device__ float g_lp[B];

// ---------------- f32x2 helpers ---------------------------------------------
__device__ __forceinline__ u64 addf32x2(u64 a, u64 b) {
    u64 r;
    asm("add.rn.f32x2 %0, %1, %2;" : "=l"(r) : "l"(a), "l"(b));
    return r;
}
__device__ __forceinline__ u64 dupf(float f) {
    u32 u = __float_as_uint(f);
    return (u64)u | ((u64)u << 32);
}
__device__ __forceinline__ float lo32f(u64 v) { return __uint_as_float((u32)v); }
__device__ __forceinline__ float hi32f(u64 v) { return __uint_as_float((u32)(v >> 32)); }

// ---------------- softmax: one block per row (4096 rows) --------------------
__global__ __launch_bounds__(256) void softmax_kernel(const float* __restrict__ ys,
                                                      const float* __restrict__ yt) {
    int row = blockIdx.x;
    const float* src = (row < B) ? (ys + (size_t)row * C) : (yt + (size_t)(row - B) * C);
    float*       dst = (row < B) ? (g_ps + (size_t)row * C) : (g_pt + (size_t)(row - B) * C);
    int tid = threadIdx.x;

    float4 x = ((const float4*)src)[tid];
    x.x *= TEMP_INV; x.y *= TEMP_INV; x.z *= TEMP_INV; x.w *= TEMP_INV;

    __shared__ float smx[8];
    __shared__ float bc;

    float m = fmaxf(fmaxf(x.x, x.y), fmaxf(x.z, x.w));
    #pragma unroll
    for (int o = 16; o > 0; o >>= 1) m = fmaxf(m, __shfl_down_sync(0xffffffffu, m, o));
    int lane = tid & 31, w = tid >> 5;
    if (lane == 0) smx[w] = m;
    __syncthreads();
    if (w == 0) {
        m = (lane < 8) ? smx[lane] : -1e30f;
        #pragma unroll
        for (int o = 4; o > 0; o >>= 1) m = fmaxf(m, __shfl_down_sync(0xffu, m, o));
        if (lane == 0) bc = m;
    }
    __syncthreads();
    m = bc;

    float4 e;
    e.x = __expf(x.x - m); e.y = __expf(x.y - m);
    e.z = __expf(x.z - m); e.w = __expf(x.w - m);
    float s = (e.x + e.y) + (e.z + e.w);

    #pragma unroll
    for (int o = 16; o > 0; o >>= 1) s += __shfl_down_sync(0xffffffffu, s, o);
    __syncthreads();
    if (lane == 0) smx[w] = s;
    __syncthreads();
    if (w == 0) {
        s = (lane < 8) ? smx[lane] : 0.0f;
        #pragma unroll
        for (int o = 4; o > 0; o >>= 1) s += __shfl_down_sync(0xffu, s, o);
        if (lane == 0) bc = s;
    }
    __syncthreads();
    float inv = __fdividef(1.0f, bc);

    e.x *= inv; e.y *= inv; e.z *= inv; e.w *= inv;
    ((float4*)dst)[tid] = e;
}

__global__ void initb_kernel() {
    int i = blockIdx.x * blockDim.x + threadIdx.x;
    if (i < B) g_b[i] = 1.0f;
}

// ---------------- cdist L1 (f32x2 packed) + K, Kt ---------------------------
// 128x128 tile, 256 threads, 8x8 per thread; pack along output-column axis.
#define KC   32
#define LDA2 33     // u64 stride for duplicated A tile
#define LDBT 130    // float stride for transposed (negated) B tile

__global__ __launch_bounds__(256, 2) void cdist_kernel() {
    __shared__ u64   As2[128 * LDA2];      // A[row][k] duplicated into both halves
    __shared__ float BsT[KC * LDBT];       // -B transposed: [k][col]

    int bi = blockIdx.y, bj = blockIdx.x;
    int tid = threadIdx.x;
    int tx = tid & 15, ty = tid >> 4;

    const float* Abase = g_ps + (size_t)(bi * 128) * C;
    const float* Bbase = g_pt + (size_t)(bj * 128) * C;

    u64 acc[8][4];
    #pragma unroll
    for (int r = 0; r < 8; r++)
        #pragma unroll
        for (int c = 0; c < 4; c++) acc[r][c] = 0ull;

    for (int k0 = 0; k0 < C; k0 += KC) {
        #pragma unroll
        for (int l = 0; l < 4; l++) {
            int v   = tid + l * 256;          // 0..1023
            int row = v >> 3;                 // 0..127
            int kq  = (v & 7) << 2;           // 0,4,..,28
            float4 a4 = *(const float4*)(Abase + (size_t)row * C + k0 + kq);
            As2[row * LDA2 + kq + 0] = dupf(a4.x);
            As2[row * LDA2 + kq + 1] = dupf(a4.y);
            As2[row * LDA2 + kq + 2] = dupf(a4.z);
            As2[row * LDA2 + kq + 3] = dupf(a4.w);
            float4 b4 = *(const float4*)(Bbase + (size_t)row * C + k0 + kq);
            BsT[(kq + 0) * LDBT + row] = -b4.x;
            BsT[(kq + 1) * LDBT + row] = -b4.y;
            BsT[(kq + 2) * LDBT + row] = -b4.z;
            BsT[(kq + 3) * LDBT + row] = -b4.w;
        }
        __syncthreads();

        #pragma unroll 4
        for (int k = 0; k < KC; k++) {
            u64 b2[4];
            const u64* bp = (const u64*)(BsT + k * LDBT + tx * 8);
            #pragma unroll
            for (int c = 0; c < 4; c++) b2[c] = bp[c];
            #pragma unroll
            for (int r = 0; r < 8; r++) {
                u64 a2 = As2[(ty * 8 + r) * LDA2 + k];
                #pragma unroll
                for (int c = 0; c < 4; c++) {
                    u64 d = addf32x2(a2, b2[c]);          // a - b (B pre-negated)
                    d &= 0x7FFFFFFF7FFFFFFFull;           // packed abs (2x LOP3, alu pipe)
                    acc[r][c] = addf32x2(acc[r][c], d);
                }
            }
        }
        __syncthreads();
    }

    // epilogue: W, K (row-major) and Kt (transposed)
    #pragma unroll
    for (int r = 0; r < 8; r++) {
        int row = bi * 128 + ty * 8 + r;
        size_t base = (size_t)row * B + bj * 128 + tx * 8;
        float wv[8];
        #pragma unroll
        for (int c = 0; c < 4; c++) { wv[2*c] = lo32f(acc[r][c]); wv[2*c+1] = hi32f(acc[r][c]); }
        #pragma unroll
        for (int q = 0; q < 2; q++) {
            float4 w4 = make_float4(wv[q*4+0], wv[q*4+1], wv[q*4+2], wv[q*4+3]);
            ((float4*)(g_W + base))[q] = w4;
            float4 k4 = make_float4(__expf(-EPS_INV * w4.x), __expf(-EPS_INV * w4.y),
                                    __expf(-EPS_INV * w4.z), __expf(-EPS_INV * w4.w));
            ((float4*)(g_K + base))[q] = k4;
        }
    }
    // Kt: per column, the thread's 8 rows are contiguous -> 2 float4 per col
    #pragma unroll
    for (int c = 0; c < 4; c++) {
        #pragma unroll
        for (int h = 0; h < 2; h++) {
            int col = bj * 128 + tx * 8 + 2 * c + h;
            float kv[8];
            #pragma unroll
            for (int r = 0; r < 8; r++) {
                float wv = h ? hi32f(acc[r][c]) : lo32f(acc[r][c]);
                kv[r] = __expf(-EPS_INV * wv);
            }
            size_t tb = (size_t)col * B + bi * 128 + ty * 8;
            ((float4*)(g_Kt + tb))[0] = make_float4(kv[0], kv[1], kv[2], kv[3]);
            ((float4*)(g_Kt + tb))[1] = make_float4(kv[4], kv[5], kv[6], kv[7]);
        }
    }
}

// ---------------- Sinkhorn matvec: vout = 1 / (M * vin) ---------------------
// 128 blocks x 512 threads, warp-per-row, one wave, shuffle-only reduction.
__global__ __launch_bounds__(512) void matvec_kernel(const float* __restrict__ M,
                                                     const float* __restrict__ vin,
                                                     float* __restrict__ vout) {
    __shared__ float4 vs[512];
    int tid = threadIdx.x, wid = tid >> 5, lane = tid & 31;
    vs[tid] = ((const float4*)vin)[tid];
    __syncthreads();

    int row = blockIdx.x * 16 + wid;
    const float4* Mr = (const float4*)(M + (size_t)row * B);
    float s = 0.0f;
    #pragma unroll
    for (int i = 0; i < 16; i++) {
        float4 m = Mr[lane + 32 * i];
        float4 v = vs[lane + 32 * i];
        s += m.x * v.x + m.y * v.y + m.z * v.z + m.w * v.w;
    }
    #pragma unroll
    for (int o = 16; o > 0; o >>= 1) s += __shfl_down_sync(0xffffffffu, s, o);
    if (lane == 0) vout[row] = __fdividef(1.0f, s);
}

// ---------------- loss: lp[row] = a[row] * sum_j K*W*b ----------------------
__global__ __launch_bounds__(512) void loss_row_kernel() {
    __shared__ float4 vs[512];
    int tid = threadIdx.x, wid = tid >> 5, lane = tid & 31;
    vs[tid] = ((const float4*)g_b)[tid];
    __syncthreads();

    int row = blockIdx.x * 16 + wid;
    const float4* Kr = (const float4*)(g_K + (size_t)row * B);
    const float4* Wr = (const float4*)(g_W + (size_t)row * B);
    float s = 0.0f;
    #pragma unroll
    for (int i = 0; i < 16; i++) {
        float4 k = Kr[lane + 32 * i];
        float4 w = Wr[lane + 32 * i];
        float4 v = vs[lane + 32 * i];
        s += k.x * w.x * v.x + k.y * w.y * v.y + k.z * w.z * v.z + k.w * w.w * v.w;
    }
    #pragma unroll
    for (int o = 16; o > 0; o >>= 1) s += __shfl_down_sync(0xffffffffu, s, o);
    if (lane == 0) g_lp[row] = g_a[row] * s;
}

__global__ __launch_bounds__(256) void loss_final_kernel(float* __restrict__ out) {
    __shared__ float sm[8];
    int tid = threadIdx.x;
    float s = 0.0f;
    #pragma unroll
    for (int l = 0; l < 8; l++) s += g_lp[tid + l * 256];
    #pragma unroll
    for (int o = 16; o > 0; o >>= 1) s += __shfl_down_sync(0xffffffffu, s, o);
    int lane = tid & 31, w = tid >> 5;
    if (lane == 0) sm[w] = s;
    __syncthreads();
    if (w == 0) {
        s = (lane < 8) ? sm[lane] : 0.0f;
        #pragma unroll
        for (int o = 4; o > 0; o >>= 1) s += __shfl_down_sync(0xffu, s, o);
        if (lane == 0) out[0] = LOSS_SCALE * s;
    }
}

// ---------------- launcher ---------------------------------------------------
extern "C" void kernel_launch(void* const* d_in, const int* in_sizes, int n_in,
                              void* d_out, int out_size) {
    const float* ys = (const float*)d_in[0];
    const float* yt = (const float*)d_in[1];
    float* out = (float*)d_out;

    softmax_kernel<<<2 * B, 256>>>(ys, yt);
    initb_kernel<<<8, 256>>>();
    cdist_kernel<<<dim3(16, 16), 256>>>();

    float* K  = nullptr; float* Kt = nullptr; float* a = nullptr; float* b = nullptr;
    cudaGetSymbolAddress((void**)&K,  g_K);
    cudaGetSymbolAddress((void**)&Kt, g_Kt);
    cudaGetSymbolAddress((void**)&a,  g_a);
    cudaGetSymbolAddress((void**)&b,  g_b);

    for (int it = 0; it < N_ITERS; it++) {
        matvec_kernel<<<128, 512>>>(K,  b, a);   // a = 1/(K b)
        matvec_kernel<<<128, 512>>>(Kt, a, b);   // b = 1/(K^T a)
    }

    loss_row_kernel<<<128, 512>>>();
    loss_final_kernel<<<1, 256>>>(out);
}